// round 1
// baseline (speedup 1.0000x reference)
#include <cuda_runtime.h>

// Problem constants (fixed by the reference)
#define BB      8
#define NC      2048
#define YD      8
#define MM      16384      // 128*128 grid points
#define NCHUNK  256        // context points staged per SMEM chunk
#define TPB     256        // threads per block
#define MPT     2          // grid points per thread (f32x2 packing over m)
#define MPB     (TPB*MPT)  // 512 grid points per block

typedef unsigned long long u64;

__device__ __forceinline__ u64 pack2(float lo, float hi) {
    u64 r;
    asm("mov.b64 %0, {%1, %2};" : "=l"(r) : "f"(lo), "f"(hi));
    return r;
}
__device__ __forceinline__ float2 unpack2(u64 v) {
    float2 f;
    asm("mov.b64 {%0, %1}, %2;" : "=f"(f.x), "=f"(f.y) : "l"(v));
    return f;
}
__device__ __forceinline__ u64 fma2(u64 a, u64 b, u64 c) {
    u64 d;
    asm("fma.rn.f32x2 %0, %1, %2, %3;" : "=l"(d) : "l"(a), "l"(b), "l"(c));
    return d;
}
__device__ __forceinline__ u64 add2(u64 a, u64 b) {
    u64 d;
    asm("add.rn.f32x2 %0, %1, %2;" : "=l"(d) : "l"(a), "l"(b));
    return d;
}
__device__ __forceinline__ float ex2f(float x) {
    float y;
    asm("ex2.approx.f32 %0, %1;" : "=f"(y) : "f"(x));
    return y;
}
__device__ __forceinline__ float rcpf(float x) {
    float y;
    asm("rcp.approx.f32 %0, %1;" : "=f"(y) : "f"(x));
    return y;
}

// SMEM layout per staged context point n (24 floats = 96B, LDS.128-friendly):
// [p,p, qx,qx, qy,qy, y0,y0, y1,y1, ..., y7,y7, 0,0]
// All values pre-duplicated so every f32x2 operand loads directly.
#define NSTRIDE 24

__global__ void __launch_bounds__(TPB)
rbf_kernel(const float* __restrict__ xc,
           const float* __restrict__ yc,
           const float* __restrict__ grid,
           const float* __restrict__ sigma,
           float* __restrict__ out)
{
    __shared__ __align__(16) float s[NCHUNK * NSTRIDE];

    const int tid   = threadIdx.x;
    const int bperb = MM / MPB;                 // 32 blocks per batch
    const int b     = blockIdx.x / bperb;
    const int mblk  = (blockIdx.x % bperb) * MPB;
    const int m0    = mblk + tid * MPT;         // even; m0,m0+1 owned by this thread

    const float sg = sigma[0];
    // w = exp(-0.5*d2/sg^2) = exp2(cc*d2), cc = -0.5*log2(e)/sg^2
    const float cc = -0.5f * 1.4426950408889634f / (sg * sg);

    // Thread-constant packed grid coords + base term cc*||g||^2
    const float gx0 = grid[2 * m0 + 0], gy0 = grid[2 * m0 + 1];
    const float gx1 = grid[2 * m0 + 2], gy1 = grid[2 * m0 + 3];
    const u64 gx2 = pack2(gx0, gx1);
    const u64 gy2 = pack2(gy0, gy1);
    const u64 bg2 = pack2(cc * (gx0 * gx0 + gy0 * gy0),
                          cc * (gx1 * gx1 + gy1 * gy1));

    u64 dens = 0ull;           // {0.f, 0.f}
    u64 acc[YD];
#pragma unroll
    for (int k = 0; k < YD; k++) acc[k] = 0ull;

    const float2* xcb = (const float2*)(xc) + (size_t)b * NC;
    const float4* ycb = (const float4*)(yc) + (size_t)b * NC * 2;

    for (int chunk = 0; chunk < NC / NCHUNK; chunk++) {
        __syncthreads();
        // ---- stage: one context point per thread (TPB == NCHUNK) ----
        {
            const int n = chunk * NCHUNK + tid;
            const float2 xv = xcb[n];
            const float4 ya = ycb[2 * n + 0];
            const float4 yb = ycb[2 * n + 1];
            const float p  = cc * (xv.x * xv.x + xv.y * xv.y);
            const float qx = -2.0f * cc * xv.x;
            const float qy = -2.0f * cc * xv.y;
            float4* d4 = (float4*)(s + tid * NSTRIDE);
            d4[0] = make_float4(p,    p,    qx,   qx);
            d4[1] = make_float4(qy,   qy,   ya.x, ya.x);
            d4[2] = make_float4(ya.y, ya.y, ya.z, ya.z);
            d4[3] = make_float4(ya.w, ya.w, yb.x, yb.x);
            d4[4] = make_float4(yb.y, yb.y, yb.z, yb.z);
            d4[5] = make_float4(yb.w, yb.w, 0.0f, 0.0f);
        }
        __syncthreads();

        // ---- main loop: 256 context points, 2 grid points per thread ----
#pragma unroll 4
        for (int j = 0; j < NCHUNK; j++) {
            const ulonglong2* sp = (const ulonglong2*)(s + j * NSTRIDE);
            const ulonglong2 v0 = sp[0];   // {p2, qx2}
            const ulonglong2 v1 = sp[1];   // {qy2, y0d}
            const ulonglong2 v2 = sp[2];   // {y1d, y2d}
            const ulonglong2 v3 = sp[3];   // {y3d, y4d}
            const ulonglong2 v4 = sp[4];   // {y5d, y6d}
            const ulonglong2 v5 = sp[5];   // {y7d, --}

            u64 t = fma2(v1.x, gy2, v0.x); // qy*gy + p
            t = fma2(v0.y, gx2, t);        // + qx*gx
            t = add2(t, bg2);              // + cc*||g||^2  == cc*d2 (packed over 2 m)

            const float2 tf = unpack2(t);
            const u64 w2 = pack2(ex2f(tf.x), ex2f(tf.y));

            dens   = add2(dens, w2);
            acc[0] = fma2(v1.y, w2, acc[0]);
            acc[1] = fma2(v2.x, w2, acc[1]);
            acc[2] = fma2(v2.y, w2, acc[2]);
            acc[3] = fma2(v3.x, w2, acc[3]);
            acc[4] = fma2(v3.y, w2, acc[4]);
            acc[5] = fma2(v4.x, w2, acc[5]);
            acc[6] = fma2(v4.y, w2, acc[6]);
            acc[7] = fma2(v5.x, w2, acc[7]);
        }
    }

    // ---- epilogue: density + normalized signal, 2 consecutive m per thread ----
    float* outp = out + (size_t)b * 9 * MM;
    const float2 dv = unpack2(dens);
    *(float2*)(outp + m0) = dv;
    const float i0 = rcpf(dv.x + 1e-5f);
    const float i1 = rcpf(dv.y + 1e-5f);
#pragma unroll
    for (int k = 0; k < YD; k++) {
        const float2 av = unpack2(acc[k]);
        float2 r;
        r.x = av.x * i0;
        r.y = av.y * i1;
        *(float2*)(outp + (size_t)(1 + k) * MM + m0) = r;
    }
}

extern "C" void kernel_launch(void* const* d_in, const int* in_sizes, int n_in,
                              void* d_out, int out_size)
{
    const float* xc    = (const float*)d_in[0];  // (8, 2048, 2)
    const float* yc    = (const float*)d_in[1];  // (8, 2048, 8)
    const float* grid  = (const float*)d_in[2];  // (1, 16384, 2)
    const float* sigma = (const float*)d_in[3];  // scalar
    float* out = (float*)d_out;                  // (8, 9, 128, 128)

    const int blocks = BB * (MM / MPB);          // 256
    rbf_kernel<<<blocks, TPB>>>(xc, yc, grid, sigma, out);
}

// round 2
// speedup vs baseline: 1.2470x; 1.2470x over previous
#include <cuda_runtime.h>

// Problem constants (fixed by the reference)
#define BB      8
#define NC      2048
#define YD      8
#define MM      16384      // 128*128 grid points
#define GR      128        // grid res per axis
#define NSPLIT  2
#define NPER    (NC / NSPLIT)   // 1024 context points per split
#define CHUNK   256             // context points staged per SMEM chunk
#define TPB     128             // threads per main-kernel block

typedef unsigned long long u64;

__device__ __forceinline__ u64 pack2(float lo, float hi) {
    u64 r;
    asm("mov.b64 %0, {%1, %2};" : "=l"(r) : "f"(lo), "f"(hi));
    return r;
}
__device__ __forceinline__ float2 unpack2(u64 v) {
    float2 f;
    asm("mov.b64 {%0, %1}, %2;" : "=f"(f.x), "=f"(f.y) : "l"(v));
    return f;
}
__device__ __forceinline__ u64 fma2(u64 a, u64 b, u64 c) {
    u64 d;
    asm("fma.rn.f32x2 %0, %1, %2, %3;" : "=l"(d) : "l"(a), "l"(b), "l"(c));
    return d;
}
__device__ __forceinline__ u64 add2(u64 a, u64 b) {
    u64 d;
    asm("add.rn.f32x2 %0, %1, %2;" : "=l"(d) : "l"(a), "l"(b));
    return d;
}
__device__ __forceinline__ u64 mul2(u64 a, u64 b) {
    u64 d;
    asm("mul.rn.f32x2 %0, %1, %2;" : "=l"(d) : "l"(a), "l"(b));
    return d;
}
__device__ __forceinline__ float ex2f(float x) {
    float y;
    asm("ex2.approx.f32 %0, %1;" : "=f"(y) : "f"(x));
    return y;
}
__device__ __forceinline__ float rcpf(float x) {
    float y;
    asm("rcp.approx.f32 %0, %1;" : "=f"(y) : "f"(x));
    return y;
}

// Unnormalized partial sums: [split][b][1+YD][M]
__device__ float g_scratch[NSPLIT][BB][1 + YD][MM];

// SMEM layout per staged context point n (24 floats = 96B, all LDS.128-friendly,
// everything pre-duplicated for direct f32x2 consumption):
// {a1,a1,a0,a0} {b1,b1,b0,b0} {y0,y0,y1,y1} {y2,y2,y3,y3} {y4,y4,y5,y5} {y6,y6,y7,y7}
// where a1=-2cc*x, a0=cc*x^2, b1=-2cc*y, b0=cc*y^2,  cc = -0.5*log2(e)/sigma^2
#define NSTRIDE 24

__global__ void __launch_bounds__(TPB)
rbf_main(const float* __restrict__ xc,
         const float* __restrict__ yc,
         const float* __restrict__ grid,
         const float* __restrict__ sigma)
{
    __shared__ __align__(16) float s[CHUNK * NSTRIDE];

    const int tid   = threadIdx.x;
    const int bx    = blockIdx.x;          // [0, 256)
    const int b     = bx >> 5;             // batch
    const int rem   = bx & 31;
    const int slab  = rem >> 1;            // 16 slabs of 8 rows
    const int split = rem & 1;             // n-split

    const int jp    = tid & 63;            // 64 j-pairs cover 128 j
    const int grp   = tid >> 6;            // 2 groups of 4 rows
    const int j0    = jp * 2;
    const int rbase = slab * 8 + grp * 4;  // 4 consecutive grid rows

    const float sg = sigma[0];
    const float cc = -0.5f * 1.4426950408889634f / (sg * sg);

    // Thread-constant grid terms (from the actual grid input, row 0 for gx)
    const float gx0 = grid[2 * j0];
    const float gx1 = grid[2 * (j0 + 1)];
    const float gy0 = grid[2 * ((rbase + 0) * GR) + 1];
    const float gy1 = grid[2 * ((rbase + 1) * GR) + 1];
    const float gy2v = grid[2 * ((rbase + 2) * GR) + 1];
    const float gy3v = grid[2 * ((rbase + 3) * GR) + 1];

    const u64 gx2   = pack2(gx0, gx1);
    const u64 cgx2  = pack2(cc * gx0 * gx0, cc * gx1 * gx1);
    const u64 gyA2  = pack2(gy0, gy1);
    const u64 gyB2  = pack2(gy2v, gy3v);
    const u64 cgyA2 = pack2(cc * gy0 * gy0, cc * gy1 * gy1);
    const u64 cgyB2 = pack2(cc * gy2v * gy2v, cc * gy3v * gy3v);

    u64 dens[4];
    u64 acc[4][YD];
#pragma unroll
    for (int i = 0; i < 4; i++) {
        dens[i] = 0ull;
#pragma unroll
        for (int k = 0; k < YD; k++) acc[i][k] = 0ull;
    }

    const float2* xcb = (const float2*)(xc) + (size_t)b * NC;
    const float4* ycb = (const float4*)(yc) + (size_t)b * NC * 2;
    const int nbase = split * NPER;

    for (int chunk = 0; chunk < NPER / CHUNK; chunk++) {
        __syncthreads();
        // ---- stage: 2 context points per thread (TPB*2 == CHUNK) ----
#pragma unroll
        for (int h = 0; h < 2; h++) {
            const int idx = tid + h * TPB;
            const int n = nbase + chunk * CHUNK + idx;
            const float2 xv = xcb[n];
            const float4 ya = ycb[2 * n + 0];
            const float4 yb = ycb[2 * n + 1];
            const float a1 = -2.0f * cc * xv.x;
            const float a0 = cc * xv.x * xv.x;
            const float b1 = -2.0f * cc * xv.y;
            const float b0 = cc * xv.y * xv.y;
            float4* d4 = (float4*)(s + idx * NSTRIDE);
            d4[0] = make_float4(a1,   a1,   a0,   a0);
            d4[1] = make_float4(b1,   b1,   b0,   b0);
            d4[2] = make_float4(ya.x, ya.x, ya.y, ya.y);
            d4[3] = make_float4(ya.z, ya.z, ya.w, ya.w);
            d4[4] = make_float4(yb.x, yb.x, yb.y, yb.y);
            d4[5] = make_float4(yb.z, yb.z, yb.w, yb.w);
        }
        __syncthreads();

        // ---- main loop: each n feeds a 2(j) x 4(i) register tile ----
#pragma unroll 4
        for (int nn = 0; nn < CHUNK; nn++) {
            const ulonglong2* sp = (const ulonglong2*)(s + nn * NSTRIDE);
            const ulonglong2 v0 = sp[0];   // {a1d, a0d}
            const ulonglong2 v1 = sp[1];   // {b1d, b0d}
            const ulonglong2 v2 = sp[2];   // {y0d, y1d}
            const ulonglong2 v3 = sp[3];   // {y2d, y3d}
            const ulonglong2 v4 = sp[4];   // {y4d, y5d}
            const ulonglong2 v5 = sp[5];   // {y6d, y7d}

            const u64 argx  = add2(fma2(v0.x, gx2,  v0.y), cgx2);
            const u64 argyA = add2(fma2(v1.x, gyA2, v1.y), cgyA2);
            const u64 argyB = add2(fma2(v1.x, gyB2, v1.y), cgyB2);

            const float2 fx = unpack2(argx);
            const u64 wxp = pack2(ex2f(fx.x), ex2f(fx.y));
            const float2 fA = unpack2(argyA);
            const float2 fB = unpack2(argyB);
            const float wy0 = ex2f(fA.x), wy1 = ex2f(fA.y);
            const float wy2 = ex2f(fB.x), wy3 = ex2f(fB.y);

            const u64 w0 = mul2(wxp, pack2(wy0, wy0));
            const u64 w1 = mul2(wxp, pack2(wy1, wy1));
            const u64 w2 = mul2(wxp, pack2(wy2, wy2));
            const u64 w3 = mul2(wxp, pack2(wy3, wy3));

            dens[0] = add2(dens[0], w0);
            dens[1] = add2(dens[1], w1);
            dens[2] = add2(dens[2], w2);
            dens[3] = add2(dens[3], w3);

#pragma unroll
            for (int i = 0; i < 4; i++) {
                const u64 wi = (i == 0) ? w0 : (i == 1) ? w1 : (i == 2) ? w2 : w3;
                acc[i][0] = fma2(v2.x, wi, acc[i][0]);
                acc[i][1] = fma2(v2.y, wi, acc[i][1]);
                acc[i][2] = fma2(v3.x, wi, acc[i][2]);
                acc[i][3] = fma2(v3.y, wi, acc[i][3]);
                acc[i][4] = fma2(v4.x, wi, acc[i][4]);
                acc[i][5] = fma2(v4.y, wi, acc[i][5]);
                acc[i][6] = fma2(v5.x, wi, acc[i][6]);
                acc[i][7] = fma2(v5.y, wi, acc[i][7]);
            }
        }
    }

    // ---- epilogue: write unnormalized partials to scratch ----
    float* base = &g_scratch[split][b][0][0];
#pragma unroll
    for (int i = 0; i < 4; i++) {
        const int m0 = (rbase + i) * GR + j0;
        *(float2*)(base + m0) = unpack2(dens[i]);
#pragma unroll
        for (int k = 0; k < YD; k++) {
            *(float2*)(base + (size_t)(1 + k) * MM + m0) = unpack2(acc[i][k]);
        }
    }
}

// Combine splits + normalize. One thread per 2 grid points.
__global__ void __launch_bounds__(256)
rbf_combine(float* __restrict__ out)
{
    const int t = blockIdx.x * blockDim.x + threadIdx.x;  // [0, B*M/2)
    const int b  = t >> 13;              // M/2 = 8192 pairs per batch
    const int m0 = (t & 8191) * 2;

    const float2* s0 = (const float2*)&g_scratch[0][b][0][m0];
    const float2* s1 = (const float2*)&g_scratch[1][b][0][m0];
    // row stride in float2 units: MM/2
    const float2 d0 = s0[0], d1 = s1[0];
    float2 d;
    d.x = d0.x + d1.x;
    d.y = d0.y + d1.y;

    float* outp = out + (size_t)b * (1 + YD) * MM;
    *(float2*)(outp + m0) = d;
    const float i0 = rcpf(d.x + 1e-5f);
    const float i1 = rcpf(d.y + 1e-5f);
#pragma unroll
    for (int k = 1; k <= YD; k++) {
        const float2 a0 = s0[(size_t)k * (MM / 2)];
        const float2 a1 = s1[(size_t)k * (MM / 2)];
        float2 r;
        r.x = (a0.x + a1.x) * i0;
        r.y = (a0.y + a1.y) * i1;
        *(float2*)(outp + (size_t)k * MM + m0) = r;
    }
}

extern "C" void kernel_launch(void* const* d_in, const int* in_sizes, int n_in,
                              void* d_out, int out_size)
{
    const float* xc    = (const float*)d_in[0];  // (8, 2048, 2)
    const float* yc    = (const float*)d_in[1];  // (8, 2048, 8)
    const float* grid  = (const float*)d_in[2];  // (1, 16384, 2)
    const float* sigma = (const float*)d_in[3];  // scalar
    float* out = (float*)d_out;                  // (8, 9, 128, 128)

    rbf_main<<<BB * 16 * NSPLIT, TPB>>>(xc, yc, grid, sigma);   // 256 CTAs
    rbf_combine<<<(BB * MM / 2) / 256, 256>>>(out);             // 256 CTAs
}

// round 4
// speedup vs baseline: 6.0735x; 4.8704x over previous
#include <cuda_runtime.h>
#include <cuda_fp16.h>
#include <cstdint>

#define BB 8
#define NC 2048
#define YD 8
#define GR 128
#define MM (GR*GR)
#define KC 64            // K per chunk (64 halfs = 128B rows)
#define NCHK (NC/KC)     // 32 chunks

// ---- device scratch ----
__device__ __half g_w[2][BB][GR][NC];      // [axis(0=x,1=y)][b][row][n]  8MB
__device__ __half g_yl[BB][YD + 1][NC];    // [b][ych][n], ych 0 -> 1.0
__device__ float  g_s[BB][YD + 1][MM];     // unnormalized GEMM output

// ---- helpers ----
__device__ __forceinline__ float ex2f(float x) {
    float y; asm("ex2.approx.f32 %0, %1;" : "=f"(y) : "f"(x)); return y;
}
__device__ __forceinline__ float rcpf(float x) {
    float y; asm("rcp.approx.f32 %0, %1;" : "=f"(y) : "f"(x)); return y;
}
__device__ __forceinline__ uint32_t s2u(const void* p) {
    uint32_t a;
    asm("{ .reg .u64 t; cvta.to.shared.u64 t, %1; cvt.u32.u64 %0, t; }" : "=r"(a) : "l"(p));
    return a;
}
__device__ __forceinline__ uint32_t hmul2u(uint32_t a, uint32_t b) {
    __half2 r = __hmul2(*(__half2*)&a, *(__half2*)&b);
    return *(uint32_t*)&r;
}
#define STS128(addr, v) \
    asm volatile("st.shared.v4.b32 [%0], {%1, %2, %3, %4};" \
                 :: "r"(addr), "r"((v).x), "r"((v).y), "r"((v).z), "r"((v).w) : "memory")

__device__ __forceinline__ void ldm4(uint32_t* r, uint32_t addr) {
    asm volatile("ldmatrix.sync.aligned.m8n8.x4.shared.b16 {%0,%1,%2,%3}, [%4];"
        : "=r"(r[0]), "=r"(r[1]), "=r"(r[2]), "=r"(r[3]) : "r"(addr));
}
__device__ __forceinline__ void mma16816(float* d, const uint32_t* a, const uint32_t* bf) {
    asm volatile("mma.sync.aligned.m16n8k16.row.col.f32.f16.f16.f32 "
        "{%0,%1,%2,%3}, {%4,%5,%6,%7}, {%8,%9}, {%0,%1,%2,%3};"
        : "+f"(d[0]), "+f"(d[1]), "+f"(d[2]), "+f"(d[3])
        : "r"(a[0]), "r"(a[1]), "r"(a[2]), "r"(a[3]), "r"(bf[0]), "r"(bf[1]));
}

// =====================  precompute (weights + lifted y)  =====================
__global__ void __launch_bounds__(256)
pre_all(const float* __restrict__ xc, const float* __restrict__ yc,
        const float* __restrict__ gp, const float* __restrict__ sigma)
{
    const int bx = blockIdx.x;
    if (bx < 128) {
        // g_w[axis][b][row][n] = exp2(cc * (x_c[b,n,axis] - gcoord)^2)
        const int axis = bx >> 6;
        const int b    = (bx >> 3) & 7;
        const int rg   = bx & 7;
        const float sg = sigma[0];
        const float cc = -0.5f * 1.4426950408889634f / (sg * sg);

        __shared__ float gco[16];
        if (threadIdx.x < 16) {
            const int row = rg * 16 + threadIdx.x;
            gco[threadIdx.x] = (axis == 0) ? gp[2 * row] : gp[2 * (row * GR) + 1];
        }
        __syncthreads();

        for (int n = threadIdx.x; n < NC; n += 256) {
            const float c = xc[((size_t)b * NC + n) * 2 + axis];
#pragma unroll
            for (int rr = 0; rr < 16; rr++) {
                const float d = c - gco[rr];
                g_w[axis][b][rg * 16 + rr][n] = __float2half(ex2f(cc * d * d));
            }
        }
    } else {
        const int r   = bx - 128;        // 72 blocks
        const int b   = r / 9;
        const int ych = r % 9;
        for (int n = threadIdx.x; n < NC; n += 256) {
            const float v = (ych == 0) ? 1.0f : yc[((size_t)b * NC + n) * YD + (ych - 1)];
            g_yl[b][ych][n] = __float2half(v);
        }
    }
}

// =====================  main GEMM (mma.sync HMMA)  =====================
// CTA = (b, ych, ixh). D[iy 0..127][ix 0..63] = sum_n (yl[n]*wy[n,iy]) * wx[n,ixh*64+ix]
__global__ void __launch_bounds__(256)
rbf_gemm()
{
    __shared__ __align__(1024) char sAraw[128 * 128];  // A: 128 rows x 64 halfs (swizzled)
    __shared__ __align__(1024) char sBraw[64 * 128];   // B: 64 rows x 64 halfs (swizzled)
    const uint32_t sAb = s2u(sAraw);
    const uint32_t sBb = s2u(sBraw);

    const int tid  = threadIdx.x;
    const int wid  = tid >> 5;
    const int lane = tid & 31;
    const int warp_m = wid >> 1;     // 0..3 (32 rows each)
    const int warp_n = wid & 1;      // 0..1 (32 cols each)

    const int bx  = blockIdx.x;      // 144 = 8 * 9 * 2
    const int b   = bx / 18;
    const int r   = bx % 18;
    const int ych = r >> 1;
    const int ixh = r & 1;

    // ---- staging maps (16B segments) ----
    const int col8 = tid & 7;        // 16B segment within 128B row
    const int row0 = tid >> 3;       // 0..31
    uint32_t swA[4], swB[2];
#pragma unroll
    for (int rr = 0; rr < 4; rr++) {
        const uint32_t off = (uint32_t)(row0 + 32 * rr) * 128u + (uint32_t)col8 * 16u;
        swA[rr] = off ^ ((off >> 3) & 0x70);
    }
#pragma unroll
    for (int rr = 0; rr < 2; rr++) {
        const uint32_t off = (uint32_t)(row0 + 32 * rr) * 128u + (uint32_t)col8 * 16u;
        swB[rr] = off ^ ((off >> 3) & 0x70);
    }

    // ---- ldmatrix address components (constant per thread) ----
    // A frag f: rows warp_m*32 + f*16 + (lane&15); k-offset (lane>>4)*16 bytes
    uint32_t rbA[2], xoA[2];
#pragma unroll
    for (int f = 0; f < 2; f++) {
        const uint32_t rA = warp_m * 32 + f * 16 + (lane & 15);
        rbA[f] = sAb + rA * 128u;
        xoA[f] = (rA & 7) << 4;
    }
    const uint32_t subA = ((lane >> 4) & 1) * 16u;
    // B pair gp: rows warp_n*32 + gp*16 + ((lane>>4)&1)*8 + (lane&7); k-off ((lane>>3)&1)*16
    uint32_t rbB[2], xoB[2];
#pragma unroll
    for (int gp2 = 0; gp2 < 2; gp2++) {
        const uint32_t rB = warp_n * 32 + gp2 * 16 + ((lane >> 4) & 1) * 8 + (lane & 7);
        rbB[gp2] = sBb + rB * 128u;
        xoB[gp2] = (rB & 7) << 4;
    }
    const uint32_t subB = ((lane >> 3) & 1) * 16u;

    const uint4* __restrict__ apw = (const uint4*)&g_w[1][b][0][0];          // wy rows
    const uint4* __restrict__ bpw = (const uint4*)&g_w[0][b][ixh * 64][0];   // wx rows
    const __half* __restrict__ ylp = &g_yl[b][ych][0];

    float acc[2][4][4];
#pragma unroll
    for (int f = 0; f < 2; f++)
#pragma unroll
        for (int g = 0; g < 4; g++)
#pragma unroll
            for (int e = 0; e < 4; e++) acc[f][g][e] = 0.0f;

    uint4 ra[4], rb[2], ryl;
    {   // prefetch chunk 0
        const int k0 = col8 * 8;
#pragma unroll
        for (int rr = 0; rr < 4; rr++) ra[rr] = apw[((row0 + 32 * rr) * NC + k0) >> 3];
#pragma unroll
        for (int rr = 0; rr < 2; rr++) rb[rr] = bpw[((row0 + 32 * rr) * NC + k0) >> 3];
        ryl = *(const uint4*)(ylp + k0);
    }

    for (int c = 0; c < NCHK; c++) {
        __syncthreads();   // prior chunk's ldmatrix reads done
        // ---- stage A = yl .* wy, B = wx (swizzled) ----
#pragma unroll
        for (int rr = 0; rr < 4; rr++) {
            uint4 v;
            v.x = hmul2u(ra[rr].x, ryl.x);
            v.y = hmul2u(ra[rr].y, ryl.y);
            v.z = hmul2u(ra[rr].z, ryl.z);
            v.w = hmul2u(ra[rr].w, ryl.w);
            STS128(sAb + swA[rr], v);
        }
#pragma unroll
        for (int rr = 0; rr < 2; rr++) STS128(sBb + swB[rr], rb[rr]);

        // prefetch next chunk while this one computes
        if (c + 1 < NCHK) {
            const int k0 = (c + 1) * KC + col8 * 8;
#pragma unroll
            for (int rr = 0; rr < 4; rr++) ra[rr] = apw[((row0 + 32 * rr) * NC + k0) >> 3];
#pragma unroll
            for (int rr = 0; rr < 2; rr++) rb[rr] = bpw[((row0 + 32 * rr) * NC + k0) >> 3];
            ryl = *(const uint4*)(ylp + k0);
        }
        __syncthreads();

        // ---- compute: 4 k16 steps ----
#pragma unroll
        for (int s = 0; s < 4; s++) {
            uint32_t afr[2][4], bfr[4][2];
#pragma unroll
            for (int f = 0; f < 2; f++) {
                const uint32_t addr = rbA[f] + (((uint32_t)(s * 32) + subA) ^ xoA[f]);
                ldm4(afr[f], addr);
            }
#pragma unroll
            for (int gp2 = 0; gp2 < 2; gp2++) {
                uint32_t t[4];
                const uint32_t addr = rbB[gp2] + (((uint32_t)(s * 32) + subB) ^ xoB[gp2]);
                ldm4(t, addr);
                bfr[gp2 * 2 + 0][0] = t[0]; bfr[gp2 * 2 + 0][1] = t[1];
                bfr[gp2 * 2 + 1][0] = t[2]; bfr[gp2 * 2 + 1][1] = t[3];
            }
#pragma unroll
            for (int f = 0; f < 2; f++)
#pragma unroll
                for (int g = 0; g < 4; g++)
                    mma16816(acc[f][g], afr[f], bfr[g]);
        }
    }

    // ---- epilogue: write unnormalized result to g_s ----
    float* dst = &g_s[b][ych][0];
    const int cbase = ixh * 64 + warp_n * 32 + (lane & 3) * 2;
    const int rlo = (lane >> 2);
#pragma unroll
    for (int f = 0; f < 2; f++) {
        const int rowb = warp_m * 32 + f * 16 + rlo;
#pragma unroll
        for (int g = 0; g < 4; g++) {
            const int cc = cbase + g * 8;
            *(float2*)(dst + (size_t)rowb * GR + cc)       = make_float2(acc[f][g][0], acc[f][g][1]);
            *(float2*)(dst + (size_t)(rowb + 8) * GR + cc) = make_float2(acc[f][g][2], acc[f][g][3]);
        }
    }
}

// =====================  combine / normalize  =====================
__global__ void __launch_bounds__(256)
rbf_comb(float* __restrict__ out)
{
    const int t  = blockIdx.x * 256 + threadIdx.x;   // 32768 threads
    const int b  = t >> 12;
    const int m4 = (t & 4095) * 4;

    const float* sp = &g_s[b][0][0];
    const float4 dv = *(const float4*)(sp + m4);
    float* op = out + (size_t)b * (YD + 1) * MM;
    *(float4*)(op + m4) = dv;
    const float i0 = rcpf(dv.x + 1e-5f);
    const float i1 = rcpf(dv.y + 1e-5f);
    const float i2 = rcpf(dv.z + 1e-5f);
    const float i3 = rcpf(dv.w + 1e-5f);
#pragma unroll
    for (int ch = 1; ch <= YD; ch++) {
        float4 a = *(const float4*)(sp + (size_t)ch * MM + m4);
        a.x *= i0; a.y *= i1; a.z *= i2; a.w *= i3;
        *(float4*)(op + (size_t)ch * MM + m4) = a;
    }
}

extern "C" void kernel_launch(void* const* d_in, const int* in_sizes, int n_in,
                              void* d_out, int out_size)
{
    const float* xc    = (const float*)d_in[0];  // (8, 2048, 2)
    const float* yc    = (const float*)d_in[1];  // (8, 2048, 8)
    const float* gp    = (const float*)d_in[2];  // (1, 16384, 2)
    const float* sigma = (const float*)d_in[3];  // scalar
    float* out = (float*)d_out;                  // (8, 9, 128, 128)

    pre_all<<<200, 256>>>(xc, yc, gp, sigma);
    rbf_gemm<<<144, 256>>>();
    rbf_comb<<<128, 256>>>(out);
}

// round 5
// speedup vs baseline: 6.8290x; 1.1244x over previous
#include <cuda_runtime.h>
#include <cuda_fp16.h>
#include <cstdint>

#define BB 8
#define NC 2048
#define YD 8
#define GR 128
#define MM (GR*GR)
#define KC 64            // K per chunk (64 halfs = 128B rows)
#define KSPL 2           // K split across CTAs
#define KPER (NC/KSPL)   // 1024
#define NCHK (KPER/KC)   // 16 chunks per CTA

// ---- device scratch ----
__device__ __half g_w[2][BB][GR][NC];        // [axis(0=x,1=y)][b][row][n]
__device__ __half g_yl[BB][YD + 1][NC];      // [b][ych][n], ych 0 -> 1.0
__device__ float  g_s[KSPL][BB][YD + 1][MM]; // partial GEMM outputs

// ---- helpers ----
__device__ __forceinline__ float ex2f(float x) {
    float y; asm("ex2.approx.f32 %0, %1;" : "=f"(y) : "f"(x)); return y;
}
__device__ __forceinline__ float rcpf(float x) {
    float y; asm("rcp.approx.f32 %0, %1;" : "=f"(y) : "f"(x)); return y;
}
__device__ __forceinline__ uint32_t s2u(const void* p) {
    uint32_t a;
    asm("{ .reg .u64 t; cvta.to.shared.u64 t, %1; cvt.u32.u64 %0, t; }" : "=r"(a) : "l"(p));
    return a;
}
__device__ __forceinline__ uint32_t hmul2u(uint32_t a, uint32_t b) {
    __half2 r = __hmul2(*(__half2*)&a, *(__half2*)&b);
    return *(uint32_t*)&r;
}
#define STS128(addr, v) \
    asm volatile("st.shared.v4.b32 [%0], {%1, %2, %3, %4};" \
                 :: "r"(addr), "r"((v).x), "r"((v).y), "r"((v).z), "r"((v).w) : "memory")

__device__ __forceinline__ void ldm4(uint32_t* r, uint32_t addr) {
    asm volatile("ldmatrix.sync.aligned.m8n8.x4.shared.b16 {%0,%1,%2,%3}, [%4];"
        : "=r"(r[0]), "=r"(r[1]), "=r"(r[2]), "=r"(r[3]) : "r"(addr));
}
__device__ __forceinline__ void mma16816(float* d, const uint32_t* a, const uint32_t* bf) {
    asm volatile("mma.sync.aligned.m16n8k16.row.col.f32.f16.f16.f32 "
        "{%0,%1,%2,%3}, {%4,%5,%6,%7}, {%8,%9}, {%0,%1,%2,%3};"
        : "+f"(d[0]), "+f"(d[1]), "+f"(d[2]), "+f"(d[3])
        : "r"(a[0]), "r"(a[1]), "r"(a[2]), "r"(a[3]), "r"(bf[0]), "r"(bf[1]));
}

// =====================  precompute (weights + lifted y)  =====================
// grid = 800: [0,512) weights (axis,b,rowgroup,nsplit4); [512,800) yl (b,ych,nsplit4)
__global__ void __launch_bounds__(256)
pre_all(const float* __restrict__ xc, const float* __restrict__ yc,
        const float* __restrict__ gp, const float* __restrict__ sigma)
{
    const int bx = blockIdx.x;
    if (bx < 512) {
        const int axis = bx >> 8;
        const int b    = (bx >> 5) & 7;
        const int rg   = (bx >> 2) & 7;
        const int ns   = bx & 3;
        const float sg = sigma[0];
        const float cc = -0.5f * 1.4426950408889634f / (sg * sg);

        __shared__ float gco[16];
        if (threadIdx.x < 16) {
            const int row = rg * 16 + threadIdx.x;
            gco[threadIdx.x] = (axis == 0) ? gp[2 * row] : gp[2 * (row * GR) + 1];
        }
        __syncthreads();

#pragma unroll
        for (int h = 0; h < 2; h++) {
            const int n = ns * 512 + h * 256 + threadIdx.x;
            const float c = xc[((size_t)b * NC + n) * 2 + axis];
#pragma unroll
            for (int rr = 0; rr < 16; rr++) {
                const float d = c - gco[rr];
                g_w[axis][b][rg * 16 + rr][n] = __float2half(ex2f(cc * d * d));
            }
        }
    } else {
        const int r   = bx - 512;        // 288 = 8 * 9 * 4
        const int b   = r / 36;
        const int rr  = r % 36;
        const int ych = rr >> 2;
        const int ns  = rr & 3;
#pragma unroll
        for (int h = 0; h < 2; h++) {
            const int n = ns * 512 + h * 256 + threadIdx.x;
            const float v = (ych == 0) ? 1.0f : yc[((size_t)b * NC + n) * YD + (ych - 1)];
            g_yl[b][ych][n] = __float2half(v);
        }
    }
}

// =====================  main GEMM (mma.sync, double-buffered)  =====================
// CTA = (b, ych, ixh, ks). D[iy][ix] += sum_{n in Kslice} (yl[n]*wy[n,iy]) * wx[n,ix']
#define SA0 0
#define SA1 16384
#define SB0 32768
#define SB1 40960

__global__ void __launch_bounds__(256)
rbf_gemm()
{
    __shared__ __align__(1024) char smem[49152];
    const uint32_t sb = s2u(smem);

    const int tid  = threadIdx.x;
    const int wid  = tid >> 5;
    const int lane = tid & 31;
    const int warp_m = wid >> 1;     // 0..3
    const int warp_n = wid & 1;      // 0..1

    const int bx  = blockIdx.x;      // 288 = 8 * 9 * 2 * 2
    const int b   = bx / 36;
    const int r   = bx % 36;
    const int ych = r >> 2;
    const int ixh = (r >> 1) & 1;
    const int ks  = r & 1;

    // ---- staging maps ----
    const int col8 = tid & 7;
    const int row0 = tid >> 3;       // 0..31
    uint32_t swA[4], swB[2];
#pragma unroll
    for (int rr = 0; rr < 4; rr++) {
        const uint32_t off = (uint32_t)(row0 + 32 * rr) * 128u + (uint32_t)col8 * 16u;
        swA[rr] = off ^ ((off >> 3) & 0x70);
    }
#pragma unroll
    for (int rr = 0; rr < 2; rr++) {
        const uint32_t off = (uint32_t)(row0 + 32 * rr) * 128u + (uint32_t)col8 * 16u;
        swB[rr] = off ^ ((off >> 3) & 0x70);
    }

    // ---- ldmatrix address components (buffer-relative) ----
    uint32_t roA[2], xoA[2];
#pragma unroll
    for (int f = 0; f < 2; f++) {
        const uint32_t rA = warp_m * 32 + f * 16 + (lane & 15);
        roA[f] = rA * 128u;
        xoA[f] = (rA & 7) << 4;
    }
    const uint32_t subA = ((lane >> 4) & 1) * 16u;
    uint32_t roB[2], xoB[2];
#pragma unroll
    for (int gp2 = 0; gp2 < 2; gp2++) {
        const uint32_t rB = warp_n * 32 + gp2 * 16 + ((lane >> 4) & 1) * 8 + (lane & 7);
        roB[gp2] = rB * 128u;
        xoB[gp2] = (rB & 7) << 4;
    }
    const uint32_t subB = ((lane >> 3) & 1) * 16u;

    const uint4* __restrict__ apw = (const uint4*)&g_w[1][b][0][0];
    const uint4* __restrict__ bpw = (const uint4*)&g_w[0][b][ixh * 64][0];
    const __half* __restrict__ ylp = &g_yl[b][ych][0];
    const int kbase = ks * KPER;

    float acc[2][4][4];
#pragma unroll
    for (int f = 0; f < 2; f++)
#pragma unroll
        for (int g = 0; g < 4; g++)
#pragma unroll
            for (int e = 0; e < 4; e++) acc[f][g][e] = 0.0f;

    uint4 ra[4], rb[2], ryl;

    // load chunk c's global data into registers
    auto ldregs = [&](int c) {
        const int k0 = kbase + c * KC + col8 * 8;
#pragma unroll
        for (int rr = 0; rr < 4; rr++) ra[rr] = apw[((row0 + 32 * rr) * NC + k0) >> 3];
#pragma unroll
        for (int rr = 0; rr < 2; rr++) rb[rr] = bpw[((row0 + 32 * rr) * NC + k0) >> 3];
        ryl = *(const uint4*)(ylp + k0);
    };
    // stage registers into SMEM buffer p
    auto stage = [&](int p) {
        const uint32_t abase = sb + (p ? SA1 : SA0);
        const uint32_t bbase = sb + (p ? SB1 : SB0);
#pragma unroll
        for (int rr = 0; rr < 4; rr++) {
            uint4 v;
            v.x = hmul2u(ra[rr].x, ryl.x);
            v.y = hmul2u(ra[rr].y, ryl.y);
            v.z = hmul2u(ra[rr].z, ryl.z);
            v.w = hmul2u(ra[rr].w, ryl.w);
            STS128(abase + swA[rr], v);
        }
#pragma unroll
        for (int rr = 0; rr < 2; rr++) STS128(bbase + swB[rr], rb[rr]);
    };

    // prologue: buf0 <- chunk0; regs <- chunk1
    ldregs(0);
    stage(0);
    ldregs(1);
    __syncthreads();

    for (int c = 0; c < NCHK; c++) {
        const int p = c & 1;
        if (c + 1 < NCHK) stage(1 - p);       // STS chunk c+1 (overlaps MMA below)
        if (c + 2 < NCHK) ldregs(c + 2);      // LDG chunk c+2

        const uint32_t aB = sb + (p ? SA1 : SA0);
        const uint32_t bB = sb + (p ? SB1 : SB0);
#pragma unroll
        for (int s = 0; s < 4; s++) {
            uint32_t afr[2][4], bfr[4][2];
#pragma unroll
            for (int f = 0; f < 2; f++)
                ldm4(afr[f], aB + roA[f] + (((uint32_t)(s * 32) + subA) ^ xoA[f]));
#pragma unroll
            for (int gp2 = 0; gp2 < 2; gp2++) {
                uint32_t t[4];
                ldm4(t, bB + roB[gp2] + (((uint32_t)(s * 32) + subB) ^ xoB[gp2]));
                bfr[gp2 * 2 + 0][0] = t[0]; bfr[gp2 * 2 + 0][1] = t[1];
                bfr[gp2 * 2 + 1][0] = t[2]; bfr[gp2 * 2 + 1][1] = t[3];
            }
#pragma unroll
            for (int f = 0; f < 2; f++)
#pragma unroll
                for (int g = 0; g < 4; g++)
                    mma16816(acc[f][g], afr[f], bfr[g]);
        }
        __syncthreads();
    }

    // ---- epilogue ----
    float* dst = &g_s[ks][b][ych][0];
    const int cbase = ixh * 64 + warp_n * 32 + (lane & 3) * 2;
    const int rlo = (lane >> 2);
#pragma unroll
    for (int f = 0; f < 2; f++) {
        const int rowb = warp_m * 32 + f * 16 + rlo;
#pragma unroll
        for (int g = 0; g < 4; g++) {
            const int cc = cbase + g * 8;
            *(float2*)(dst + (size_t)rowb * GR + cc)       = make_float2(acc[f][g][0], acc[f][g][1]);
            *(float2*)(dst + (size_t)(rowb + 8) * GR + cc) = make_float2(acc[f][g][2], acc[f][g][3]);
        }
    }
}

// =====================  combine / normalize (fully parallel)  =====================
// grid = 1152: (b, ch, 16 m-blocks); thread handles 4 grid points of one channel
__global__ void __launch_bounds__(256)
rbf_comb(float* __restrict__ out)
{
    const int bx = blockIdx.x;
    const int b  = bx / 144;
    const int rr = bx % 144;
    const int ch = rr >> 4;                                // 0..8
    const int m4 = (((rr & 15) << 8) + threadIdx.x) * 4;   // 0..16380

    const float4 d0 = *(const float4*)&g_s[0][b][0][m4];
    const float4 d1 = *(const float4*)&g_s[1][b][0][m4];
    float4 dv;
    dv.x = d0.x + d1.x; dv.y = d0.y + d1.y;
    dv.z = d0.z + d1.z; dv.w = d0.w + d1.w;

    float* op = out + ((size_t)b * (YD + 1) + ch) * MM + m4;
    if (ch == 0) {
        *(float4*)op = dv;
        return;
    }
    const float4 a0 = *(const float4*)&g_s[0][b][ch][m4];
    const float4 a1 = *(const float4*)&g_s[1][b][ch][m4];
    float4 r;
    r.x = (a0.x + a1.x) * rcpf(dv.x + 1e-5f);
    r.y = (a0.y + a1.y) * rcpf(dv.y + 1e-5f);
    r.z = (a0.z + a1.z) * rcpf(dv.z + 1e-5f);
    r.w = (a0.w + a1.w) * rcpf(dv.w + 1e-5f);
    *(float4*)op = r;
}

extern "C" void kernel_launch(void* const* d_in, const int* in_sizes, int n_in,
                              void* d_out, int out_size)
{
    const float* xc    = (const float*)d_in[0];  // (8, 2048, 2)
    const float* yc    = (const float*)d_in[1];  // (8, 2048, 8)
    const float* gp    = (const float*)d_in[2];  // (1, 16384, 2)
    const float* sigma = (const float*)d_in[3];  // scalar
    float* out = (float*)d_out;                  // (8, 9, 128, 128)

    pre_all<<<800, 256>>>(xc, yc, gp, sigma);
    rbf_gemm<<<288, 256>>>();
    rbf_comb<<<1152, 256>>>(out);
}